// round 1
// baseline (speedup 1.0000x reference)
#include <cuda_runtime.h>
#include <math.h>

#define Bc  4
#define Lc  1024
#define Dc  512
#define Hc  8
#define Ec  4
#define Tc  (Bc*Lc)       // 4096 tokens

// ---------------- scratch (static device globals; no allocation) ----------------
__device__ float g_q[Tc*Dc];
__device__ float g_k[Tc*Dc];
__device__ float g_v[Tc*Dc];
__device__ float g_gate[Tc*Dc];
__device__ float g_beta[Tc*Hc];
__device__ float g_gamma[Tc*Hc];
__device__ float g_w[Tc*Ec];
__device__ float g_o[(size_t)Ec*Tc*Hc*64];
__device__ float g_core[Tc*Dc];

// ---------------- tiled fp32 GEMM: C[M,N] = act(A[M,K] @ B[K,N]) ----------------
// grid: (N/64, M/64), block 256. act: 0 = none, 1 = silu.
__global__ void gemm_kernel(const float* __restrict__ A, const float* __restrict__ B,
                            float* __restrict__ C, int K, int N, int act) {
    __shared__ float As[16][68];   // padded (+4 keeps 16B alignment, reduces STS conflicts)
    __shared__ float Bs[16][64];
    int tid = threadIdx.x;
    int tx = tid & 15;     // column group
    int ty = tid >> 4;     // row group
    int m0 = blockIdx.y * 64;
    int n0 = blockIdx.x * 64;
    int lk = tid & 15;     // A-load: k within tile
    int lm = tid >> 4;     // A-load: row base
    int bc = tid & 63;     // B-load: col
    int br = tid >> 6;     // B-load: row base

    float acc[4][4] = {};

    for (int kt = 0; kt < K; kt += 16) {
        #pragma unroll
        for (int p = 0; p < 4; p++)
            As[lk][lm + p*16] = A[(size_t)(m0 + lm + p*16)*K + kt + lk];
        #pragma unroll
        for (int p = 0; p < 4; p++)
            Bs[br + p*4][bc] = B[(size_t)(kt + br + p*4)*N + n0 + bc];
        __syncthreads();
        #pragma unroll
        for (int kk = 0; kk < 16; kk++) {
            float4 a4 = *(const float4*)&As[kk][ty*4];
            float4 b4 = *(const float4*)&Bs[kk][tx*4];
            float a[4] = {a4.x, a4.y, a4.z, a4.w};
            float b[4] = {b4.x, b4.y, b4.z, b4.w};
            #pragma unroll
            for (int i = 0; i < 4; i++)
                #pragma unroll
                for (int j = 0; j < 4; j++)
                    acc[i][j] = fmaf(a[i], b[j], acc[i][j]);
        }
        __syncthreads();
    }

    #pragma unroll
    for (int i = 0; i < 4; i++) {
        int m = m0 + ty*4 + i;
        #pragma unroll
        for (int j = 0; j < 4; j++) {
            int n = n0 + tx*4 + j;
            float x = acc[i][j];
            if (act == 1) x = x / (1.f + expf(-x));  // silu
            C[(size_t)m*N + n] = x;
        }
    }
}

// ---------------- l2norm over each head-group of 64 (q then k) ----------------
__global__ void l2norm_kernel() {
    int gid  = (blockIdx.x * blockDim.x + threadIdx.x) >> 5;
    int lane = threadIdx.x & 31;
    float* buf = (gid < Tc*Hc) ? g_q : g_k;
    int grp = (gid < Tc*Hc) ? gid : gid - Tc*Hc;
    float* p = buf + (size_t)grp * 64;
    float x0 = p[lane], x1 = p[lane + 32];
    float ss = x0*x0 + x1*x1;
    #pragma unroll
    for (int off = 16; off; off >>= 1) ss += __shfl_xor_sync(~0u, ss, off);
    float r = rsqrtf(ss + 1e-6f);
    p[lane]      = x0 * r;
    p[lane + 32] = x1 * r;
}

// ---------------- small projections: beta, gamma, router top-2 ----------------
__global__ void smallproj_kernel(const float* __restrict__ h,
                                 const float* __restrict__ Wb,
                                 const float* __restrict__ Wa,
                                 const float* __restrict__ Wgate,
                                 const float* __restrict__ A_log,
                                 const float* __restrict__ dt_bias) {
    int warp = (blockIdx.x * blockDim.x + threadIdx.x) >> 5;  // token id
    int lane = threadIdx.x & 31;
    if (warp >= Tc) return;
    const float* hrow = h + (size_t)warp * Dc;

    float accB[Hc] = {}, accA[Hc] = {}, accG[Ec] = {};
    for (int i = 0; i < Dc/32; i++) {
        int r = i*32 + lane;
        float hv = hrow[r];
        #pragma unroll
        for (int c = 0; c < Hc; c++) {
            accB[c] = fmaf(hv, Wb[r*Hc + c], accB[c]);
            accA[c] = fmaf(hv, Wa[r*Hc + c], accA[c]);
        }
        #pragma unroll
        for (int c = 0; c < Ec; c++)
            accG[c] = fmaf(hv, Wgate[r*Ec + c], accG[c]);
    }
    #pragma unroll
    for (int c = 0; c < Hc; c++) {
        #pragma unroll
        for (int off = 16; off; off >>= 1) {
            accB[c] += __shfl_xor_sync(~0u, accB[c], off);
            accA[c] += __shfl_xor_sync(~0u, accA[c], off);
        }
    }
    #pragma unroll
    for (int c = 0; c < Ec; c++)
        #pragma unroll
        for (int off = 16; off; off >>= 1)
            accG[c] += __shfl_xor_sync(~0u, accG[c], off);

    if (lane < Hc) {
        int c = lane;
        g_beta[warp*Hc + c] = 1.f / (1.f + expf(-accB[c]));
        float x = accA[c] + dt_bias[c];
        float sp = (x > 20.f) ? x : log1pf(expf(x));
        g_gamma[warp*Hc + c] = -expf(A_log[c]) * sp;
    }
    if (lane == 0) {
        float m = fmaxf(fmaxf(accG[0], accG[1]), fmaxf(accG[2], accG[3]));
        float p[4]; float s = 0.f;
        #pragma unroll
        for (int e = 0; e < 4; e++) { p[e] = expf(accG[e] - m); s += p[e]; }
        #pragma unroll
        for (int e = 0; e < 4; e++) p[e] /= s;
        int i1 = 0;
        for (int e = 1; e < 4; e++) if (p[e] > p[i1]) i1 = e;
        int i2 = -1;
        for (int e = 0; e < 4; e++) { if (e == i1) continue; if (i2 < 0 || p[e] > p[i2]) i2 = e; }
        float den = p[i1] + p[i2];
        float w[4] = {0.f, 0.f, 0.f, 0.f};
        w[i1] = p[i1] / den;
        w[i2] = p[i2] / den;
        #pragma unroll
        for (int e = 0; e < 4; e++) g_w[warp*Ec + e] = w[e];
    }
}

// ---------------- sequential delta-rule scan, one block per (e,b,h) ----------------
// 64 threads; thread j owns state column S[:, j] (64 regs). Skips non-routed tokens.
__global__ void __launch_bounds__(64) scan_kernel() {
    int idx = blockIdx.x;            // 0..127
    int e = idx >> 5;                // /32
    int rem = idx & 31;
    int b = rem >> 3;
    int h = rem & 7;
    int j = threadIdx.x;

    __shared__ float ksh[64], qsh[64];
    float S[64];
    #pragma unroll
    for (int i = 0; i < 64; i++) S[i] = 0.f;

    for (int l = 0; l < Lc; l++) {
        int t = b*Lc + l;
        float w = g_w[t*Ec + e];
        if (w <= 0.f) continue;      // uniform across block: no barrier divergence

        __syncthreads();
        size_t base = ((size_t)t*Hc + h) * 64;
        ksh[j] = g_k[base + j];
        qsh[j] = g_q[base + j];
        __syncthreads();

        float vj  = g_v[base + j];
        float eg  = expf(g_gamma[t*Hc + h]);
        float bet = g_beta[t*Hc + h];

        float kv0 = 0.f, kv1 = 0.f, kv2 = 0.f, kv3 = 0.f;
        #pragma unroll
        for (int i = 0; i < 64; i += 4) {
            float4 k4 = *(const float4*)&ksh[i];
            S[i]   *= eg; S[i+1] *= eg; S[i+2] *= eg; S[i+3] *= eg;
            kv0 = fmaf(k4.x, S[i],   kv0);
            kv1 = fmaf(k4.y, S[i+1], kv1);
            kv2 = fmaf(k4.z, S[i+2], kv2);
            kv3 = fmaf(k4.w, S[i+3], kv3);
        }
        float delta = (vj - ((kv0 + kv1) + (kv2 + kv3))) * bet;

        float o0 = 0.f, o1 = 0.f, o2 = 0.f, o3 = 0.f;
        #pragma unroll
        for (int i = 0; i < 64; i += 4) {
            float4 k4 = *(const float4*)&ksh[i];
            float4 q4 = *(const float4*)&qsh[i];
            S[i]   = fmaf(k4.x, delta, S[i]);
            S[i+1] = fmaf(k4.y, delta, S[i+1]);
            S[i+2] = fmaf(k4.z, delta, S[i+2]);
            S[i+3] = fmaf(k4.w, delta, S[i+3]);
            o0 = fmaf(q4.x, S[i],   o0);
            o1 = fmaf(q4.y, S[i+1], o1);
            o2 = fmaf(q4.z, S[i+2], o2);
            o3 = fmaf(q4.w, S[i+3], o3);
        }
        g_o[(((size_t)e*Tc + t)*Hc + h)*64 + j] = ((o0 + o1) + (o2 + o3)) * 0.125f;
    }
}

// ---------------- combine experts + gated RMSNorm ----------------
__global__ void combine_kernel(const float* __restrict__ onw) {
    int t    = blockIdx.x;
    int h    = threadIdx.x >> 5;
    int lane = threadIdx.x & 31;

    float w[4];
    #pragma unroll
    for (int e = 0; e < 4; e++) w[e] = g_w[t*Ec + e];

    float c0 = 0.f, c1 = 0.f;
    #pragma unroll
    for (int e = 0; e < 4; e++) {
        if (w[e] > 0.f) {
            size_t base = (((size_t)e*Tc + t)*Hc + h) * 64;
            c0 = fmaf(w[e], g_o[base + lane],      c0);
            c1 = fmaf(w[e], g_o[base + lane + 32], c1);
        }
    }
    float ss = c0*c0 + c1*c1;
    #pragma unroll
    for (int off = 16; off; off >>= 1) ss += __shfl_xor_sync(~0u, ss, off);
    float r = rsqrtf(ss * (1.f/64.f) + 1e-5f);

    size_t gb = (size_t)t*Dc + h*64;
    float gt0 = g_gate[gb + lane];        // silu already applied in GEMM epilogue
    float gt1 = g_gate[gb + lane + 32];
    g_core[gb + lane]      = c0 * r * onw[lane]      * gt0;
    g_core[gb + lane + 32] = c1 * r * onw[lane + 32] * gt1;
}

// ---------------- launcher ----------------
extern "C" void kernel_launch(void* const* d_in, const int* in_sizes, int n_in,
                              void* d_out, int out_size) {
    const float* h     = (const float*)d_in[0];
    const float* Wq    = (const float*)d_in[1];
    const float* Wgate = (const float*)d_in[2];
    const float* Wk    = (const float*)d_in[3];
    const float* Wv    = (const float*)d_in[4];
    const float* Wb    = (const float*)d_in[5];
    const float* Wa    = (const float*)d_in[6];
    const float* A_log = (const float*)d_in[7];
    const float* dtb   = (const float*)d_in[8];
    const float* Wg    = (const float*)d_in[9];
    const float* onw   = (const float*)d_in[10];
    const float* Wo    = (const float*)d_in[11];
    float* out = (float*)d_out;

    float *pq, *pk, *pv, *pg, *pcore;
    cudaGetSymbolAddress((void**)&pq, g_q);
    cudaGetSymbolAddress((void**)&pk, g_k);
    cudaGetSymbolAddress((void**)&pv, g_v);
    cudaGetSymbolAddress((void**)&pg, g_gate);
    cudaGetSymbolAddress((void**)&pcore, g_core);

    dim3 gg(Dc/64, Tc/64);  // (8, 64)
    gemm_kernel<<<gg, 256>>>(h, Wq, pq, Dc, Dc, 1);
    gemm_kernel<<<gg, 256>>>(h, Wk, pk, Dc, Dc, 1);
    gemm_kernel<<<gg, 256>>>(h, Wv, pv, Dc, Dc, 1);
    gemm_kernel<<<gg, 256>>>(h, Wg, pg, Dc, Dc, 1);
    l2norm_kernel<<<(2*Tc*Hc)/8, 256>>>();
    smallproj_kernel<<<Tc/8, 256>>>(h, Wb, Wa, Wgate, A_log, dtb);
    scan_kernel<<<128, 64>>>();
    combine_kernel<<<Tc, 256>>>(onw);
    gemm_kernel<<<gg, 256>>>(pcore, Wo, out, Dc, Dc, 0);
}

// round 2
// speedup vs baseline: 1.1468x; 1.1468x over previous
#include <cuda_runtime.h>
#include <math.h>

#define Bc  4
#define Lc  1024
#define Dc  512
#define Hc  8
#define Ec  4
#define Tc  (Bc*Lc)       // 4096 tokens

typedef unsigned long long u64;

__device__ __forceinline__ u64 pk2(float x, float y){ u64 r; asm("mov.b64 %0,{%1,%2};":"=l"(r):"f"(x),"f"(y)); return r; }
__device__ __forceinline__ float2 up2(u64 v){ float2 r; asm("mov.b64 {%0,%1},%2;":"=f"(r.x),"=f"(r.y):"l"(v)); return r; }
__device__ __forceinline__ u64 fma2v(u64 a,u64 b,u64 c){ u64 d; asm("fma.rn.f32x2 %0,%1,%2,%3;":"=l"(d):"l"(a),"l"(b),"l"(c)); return d; }
__device__ __forceinline__ u64 mul2v(u64 a,u64 b){ u64 d; asm("mul.rn.f32x2 %0,%1,%2;":"=l"(d):"l"(a),"l"(b)); return d; }

// ---------------- scratch ----------------
__device__ float g_q[Tc*Dc];
__device__ float g_k[Tc*Dc];
__device__ float g_v[Tc*Dc];
__device__ float g_gate[Tc*Dc];
__device__ float g_beta[Tc*Hc];
__device__ float g_egamma[Tc*Hc];   // exp(g) precomputed
__device__ float g_w[Tc*Ec];
__device__ float g_o[(size_t)Ec*Tc*Hc*64];
__device__ float g_core[Tc*Dc];
__device__ int   g_list[Ec*Bc*Lc];
__device__ int   g_cnt[Ec*Bc];

// ---------------- GEMM: C[M,N] = act(A[M,K] @ B[K,N]), f32x2 packed ----------------
// BM=64, BN=64, BK=16, 128 threads, 8x4 per thread (4 row-pairs x 4 cols).
__global__ void __launch_bounds__(128) gemm_kernel(
        const float* __restrict__ A, const float* __restrict__ B,
        float* __restrict__ C, int K, int N, int act) {
    __shared__ float As[16][68];   // [k][m], padded
    __shared__ float Bs[16][64];
    int tid = threadIdx.x;
    int tx = tid & 15;      // 4 cols:  tx*4
    int ty = tid >> 4;      // 8 rows:  ty*8
    int m0 = blockIdx.y * 64;
    int n0 = blockIdx.x * 64;

    u64 acc2[4][4];
    #pragma unroll
    for (int i = 0; i < 4; i++)
        #pragma unroll
        for (int j = 0; j < 4; j++) acc2[i][j] = 0ull;

    for (int kt = 0; kt < K; kt += 16) {
        // load A 64x16 (256 float4)
        #pragma unroll
        for (int p = 0; p < 2; p++) {
            int idx = tid + p*128;
            int m  = idx >> 2;
            int k4 = (idx & 3) * 4;
            float4 v = *(const float4*)&A[(size_t)(m0 + m)*K + kt + k4];
            As[k4+0][m] = v.x; As[k4+1][m] = v.y;
            As[k4+2][m] = v.z; As[k4+3][m] = v.w;
        }
        // load B 16x64 (256 float4)
        #pragma unroll
        for (int p = 0; p < 2; p++) {
            int idx = tid + p*128;
            int k  = idx >> 4;
            int n4 = (idx & 15) * 4;
            *(float4*)&Bs[k][n4] = *(const float4*)&B[(size_t)(kt + k)*N + n0 + n4];
        }
        __syncthreads();
        #pragma unroll
        for (int kk = 0; kk < 16; kk++) {
            u64 av[4];
            #pragma unroll
            for (int ri = 0; ri < 4; ri++)
                av[ri] = *(const u64*)&As[kk][ty*8 + 2*ri];
            float4 bv = *(const float4*)&Bs[kk][tx*4];
            u64 bb[4] = { pk2(bv.x,bv.x), pk2(bv.y,bv.y), pk2(bv.z,bv.z), pk2(bv.w,bv.w) };
            #pragma unroll
            for (int ri = 0; ri < 4; ri++)
                #pragma unroll
                for (int j = 0; j < 4; j++)
                    acc2[ri][j] = fma2v(av[ri], bb[j], acc2[ri][j]);
        }
        __syncthreads();
    }

    // epilogue
    #pragma unroll
    for (int ri = 0; ri < 4; ri++) {
        float r0[4], r1[4];
        #pragma unroll
        for (int j = 0; j < 4; j++) {
            float2 c = up2(acc2[ri][j]);
            r0[j] = c.x; r1[j] = c.y;
        }
        if (act == 1) {
            #pragma unroll
            for (int j = 0; j < 4; j++) {
                r0[j] = r0[j] / (1.f + expf(-r0[j]));
                r1[j] = r1[j] / (1.f + expf(-r1[j]));
            }
        }
        int m = m0 + ty*8 + 2*ri;
        *(float4*)&C[(size_t)m*N + n0 + tx*4]     = make_float4(r0[0],r0[1],r0[2],r0[3]);
        *(float4*)&C[(size_t)(m+1)*N + n0 + tx*4] = make_float4(r1[0],r1[1],r1[2],r1[3]);
    }
}

// ---------------- l2norm over each head-group of 64 (q then k) ----------------
__global__ void l2norm_kernel() {
    int gid  = (blockIdx.x * blockDim.x + threadIdx.x) >> 5;
    int lane = threadIdx.x & 31;
    float* buf = (gid < Tc*Hc) ? g_q : g_k;
    int grp = (gid < Tc*Hc) ? gid : gid - Tc*Hc;
    float* p = buf + (size_t)grp * 64;
    float x0 = p[lane], x1 = p[lane + 32];
    float ss = x0*x0 + x1*x1;
    #pragma unroll
    for (int off = 16; off; off >>= 1) ss += __shfl_xor_sync(~0u, ss, off);
    float r = rsqrtf(ss + 1e-6f);
    p[lane]      = x0 * r;
    p[lane + 32] = x1 * r;
}

// ---------------- small projections: beta, exp(gamma), router top-2 ----------------
__global__ void smallproj_kernel(const float* __restrict__ h,
                                 const float* __restrict__ Wb,
                                 const float* __restrict__ Wa,
                                 const float* __restrict__ Wgate,
                                 const float* __restrict__ A_log,
                                 const float* __restrict__ dt_bias) {
    int warp = (blockIdx.x * blockDim.x + threadIdx.x) >> 5;
    int lane = threadIdx.x & 31;
    if (warp >= Tc) return;
    const float* hrow = h + (size_t)warp * Dc;

    float accB[Hc] = {}, accA[Hc] = {}, accG[Ec] = {};
    for (int i = 0; i < Dc/32; i++) {
        int r = i*32 + lane;
        float hv = hrow[r];
        #pragma unroll
        for (int c = 0; c < Hc; c++) {
            accB[c] = fmaf(hv, Wb[r*Hc + c], accB[c]);
            accA[c] = fmaf(hv, Wa[r*Hc + c], accA[c]);
        }
        #pragma unroll
        for (int c = 0; c < Ec; c++)
            accG[c] = fmaf(hv, Wgate[r*Ec + c], accG[c]);
    }
    #pragma unroll
    for (int c = 0; c < Hc; c++) {
        #pragma unroll
        for (int off = 16; off; off >>= 1) {
            accB[c] += __shfl_xor_sync(~0u, accB[c], off);
            accA[c] += __shfl_xor_sync(~0u, accA[c], off);
        }
    }
    #pragma unroll
    for (int c = 0; c < Ec; c++)
        #pragma unroll
        for (int off = 16; off; off >>= 1)
            accG[c] += __shfl_xor_sync(~0u, accG[c], off);

    if (lane < Hc) {
        int c = lane;
        g_beta[warp*Hc + c] = 1.f / (1.f + expf(-accB[c]));
        float x = accA[c] + dt_bias[c];
        float sp = (x > 20.f) ? x : log1pf(expf(x));
        g_egamma[warp*Hc + c] = expf(-expf(A_log[c]) * sp);
    }
    if (lane == 0) {
        float m = fmaxf(fmaxf(accG[0], accG[1]), fmaxf(accG[2], accG[3]));
        float p[4]; float s = 0.f;
        #pragma unroll
        for (int e = 0; e < 4; e++) { p[e] = expf(accG[e] - m); s += p[e]; }
        #pragma unroll
        for (int e = 0; e < 4; e++) p[e] /= s;
        int i1 = 0;
        for (int e = 1; e < 4; e++) if (p[e] > p[i1]) i1 = e;
        int i2 = -1;
        for (int e = 0; e < 4; e++) { if (e == i1) continue; if (i2 < 0 || p[e] > p[i2]) i2 = e; }
        float den = p[i1] + p[i2];
        float w[4] = {0.f, 0.f, 0.f, 0.f};
        w[i1] = p[i1] / den;
        w[i2] = p[i2] / den;
        #pragma unroll
        for (int e = 0; e < 4; e++) g_w[warp*Ec + e] = w[e];
    }
}

// ---------------- compact routed-token lists: one block per (e,b) ----------------
__global__ void __launch_bounds__(1024) compact_kernel() {
    int eb = blockIdx.x;           // e*Bc + b
    int e = eb >> 2, b = eb & 3;
    int l = threadIdx.x;
    int warp = l >> 5, lane = l & 31;
    int t = b*Lc + l;
    bool on = g_w[t*Ec + e] > 0.f;
    unsigned mask = __ballot_sync(~0u, on);
    int pre = __popc(mask & ((1u << lane) - 1));
    __shared__ int wtot[32];
    if (lane == 31) wtot[warp] = pre + (on ? 1 : 0);
    __syncthreads();
    if (warp == 0) {
        int v = wtot[lane];
        #pragma unroll
        for (int off = 1; off < 32; off <<= 1) {
            int u = __shfl_up_sync(~0u, v, off);
            if (lane >= off) v += u;
        }
        wtot[lane] = v;
    }
    __syncthreads();
    int base = warp ? wtot[warp-1] : 0;
    if (on) g_list[eb*Lc + base + pre] = l;
    if (l == 1023) g_cnt[eb] = wtot[31];
}

// ---------------- scan: one block per (e,b,h), 256 thr = 64 cols x 4 row-groups --
__global__ void __launch_bounds__(256) scan_kernel() {
    int idx = blockIdx.x;            // 0..127
    int e = idx >> 5;
    int rem = idx & 31;
    int b = rem >> 3;
    int h = rem & 7;
    int tid = threadIdx.x;
    int j = tid & 63;                // DV column
    int r = tid >> 6;                // row group: rows 16r..16r+15
    int i0 = r << 4;

    __shared__ float ksh[64], qsh[64], vsh[64];
    __shared__ float kvpart[4][64];
    __shared__ float opart[4][64];

    u64 S2[8];
    #pragma unroll
    for (int p = 0; p < 8; p++) S2[p] = 0ull;

    int eb = e*Bc + b;
    int cnt = g_cnt[eb];
    const int* lst = &g_list[eb*Lc];

    for (int n = 0; n < cnt; n++) {
        int t = b*Lc + lst[n];
        size_t base = ((size_t)t*Hc + h) * 64;

        if (tid < 64) {
            ksh[j] = g_k[base + j];
            qsh[j] = g_q[base + j];
            vsh[j] = g_v[base + j];
        }
        __syncthreads();                          // sync B

        float eg  = g_egamma[t*Hc + h];
        float bet = g_beta[t*Hc + h];
        u64 eg2 = pk2(eg, eg);

        // phase 1: decay + kv partial
        u64 k2[8];
        u64 kv2 = 0ull;
        #pragma unroll
        for (int p = 0; p < 8; p++) {
            k2[p] = *(const u64*)&ksh[i0 + 2*p];
            S2[p] = mul2v(S2[p], eg2);
            kv2 = fma2v(k2[p], S2[p], kv2);
        }
        float2 kvf = up2(kv2);
        kvpart[r][j] = kvf.x + kvf.y;
        __syncthreads();                          // sync C

        float kvsum = kvpart[0][j] + kvpart[1][j] + kvpart[2][j] + kvpart[3][j];
        float delta = (vsh[j] - kvsum) * bet;
        u64 d2 = pk2(delta, delta);

        // phase 2: state update + output partial
        u64 o2 = 0ull;
        #pragma unroll
        for (int p = 0; p < 8; p++) {
            u64 q2 = *(const u64*)&qsh[i0 + 2*p];
            S2[p] = fma2v(k2[p], d2, S2[p]);
            o2 = fma2v(q2, S2[p], o2);
        }
        float2 of = up2(o2);
        opart[r][j] = of.x + of.y;
        __syncthreads();                          // sync D

        if (r == 0) {
            float o = opart[0][j] + opart[1][j] + opart[2][j] + opart[3][j];
            g_o[(((size_t)e*Tc + t)*Hc + h)*64 + j] = o * 0.125f;
        }
    }
}

// ---------------- combine experts + gated RMSNorm ----------------
__global__ void combine_kernel(const float* __restrict__ onw) {
    int t    = blockIdx.x;
    int h    = threadIdx.x >> 5;
    int lane = threadIdx.x & 31;

    float w[4];
    #pragma unroll
    for (int e = 0; e < 4; e++) w[e] = g_w[t*Ec + e];

    float c0 = 0.f, c1 = 0.f;
    #pragma unroll
    for (int e = 0; e < 4; e++) {
        if (w[e] > 0.f) {
            size_t base = (((size_t)e*Tc + t)*Hc + h) * 64;
            c0 = fmaf(w[e], g_o[base + lane],      c0);
            c1 = fmaf(w[e], g_o[base + lane + 32], c1);
        }
    }
    float ss = c0*c0 + c1*c1;
    #pragma unroll
    for (int off = 16; off; off >>= 1) ss += __shfl_xor_sync(~0u, ss, off);
    float r = rsqrtf(ss * (1.f/64.f) + 1e-5f);

    size_t gb = (size_t)t*Dc + h*64;
    float gt0 = g_gate[gb + lane];
    float gt1 = g_gate[gb + lane + 32];
    g_core[gb + lane]      = c0 * r * onw[lane]      * gt0;
    g_core[gb + lane + 32] = c1 * r * onw[lane + 32] * gt1;
}

// ---------------- launcher ----------------
extern "C" void kernel_launch(void* const* d_in, const int* in_sizes, int n_in,
                              void* d_out, int out_size) {
    const float* h     = (const float*)d_in[0];
    const float* Wq    = (const float*)d_in[1];
    const float* Wgate = (const float*)d_in[2];
    const float* Wk    = (const float*)d_in[3];
    const float* Wv    = (const float*)d_in[4];
    const float* Wb    = (const float*)d_in[5];
    const float* Wa    = (const float*)d_in[6];
    const float* A_log = (const float*)d_in[7];
    const float* dtb   = (const float*)d_in[8];
    const float* Wg    = (const float*)d_in[9];
    const float* onw   = (const float*)d_in[10];
    const float* Wo    = (const float*)d_in[11];
    float* out = (float*)d_out;

    float *pq, *pk, *pv, *pg, *pcore;
    cudaGetSymbolAddress((void**)&pq, g_q);
    cudaGetSymbolAddress((void**)&pk, g_k);
    cudaGetSymbolAddress((void**)&pv, g_v);
    cudaGetSymbolAddress((void**)&pg, g_gate);
    cudaGetSymbolAddress((void**)&pcore, g_core);

    dim3 gg(Dc/64, Tc/64);  // (8, 64)
    gemm_kernel<<<gg, 128>>>(h, Wq, pq, Dc, Dc, 1);
    gemm_kernel<<<gg, 128>>>(h, Wk, pk, Dc, Dc, 1);
    gemm_kernel<<<gg, 128>>>(h, Wv, pv, Dc, Dc, 1);
    gemm_kernel<<<gg, 128>>>(h, Wg, pg, Dc, Dc, 1);
    l2norm_kernel<<<(2*Tc*Hc)/8, 256>>>();
    smallproj_kernel<<<Tc/8, 256>>>(h, Wb, Wa, Wgate, A_log, dtb);
    compact_kernel<<<Ec*Bc, 1024>>>();
    scan_kernel<<<128, 256>>>();
    combine_kernel<<<Tc, 256>>>(onw);
    gemm_kernel<<<gg, 128>>>(pcore, Wo, out, Dc, Dc, 0);
}

// round 3
// speedup vs baseline: 1.2889x; 1.1240x over previous
#include <cuda_runtime.h>
#include <math.h>

#define Bc  4
#define Lc  1024
#define Dc  512
#define Hc  8
#define Ec  4
#define Tc  (Bc*Lc)       // 4096 tokens

typedef unsigned long long u64;

__device__ __forceinline__ u64 pk2(float x, float y){ u64 r; asm("mov.b64 %0,{%1,%2};":"=l"(r):"f"(x),"f"(y)); return r; }
__device__ __forceinline__ float2 up2(u64 v){ float2 r; asm("mov.b64 {%0,%1},%2;":"=f"(r.x),"=f"(r.y):"l"(v)); return r; }
__device__ __forceinline__ u64 fma2v(u64 a,u64 b,u64 c){ u64 d; asm("fma.rn.f32x2 %0,%1,%2,%3;":"=l"(d):"l"(a),"l"(b),"l"(c)); return d; }
__device__ __forceinline__ u64 mul2v(u64 a,u64 b){ u64 d; asm("mul.rn.f32x2 %0,%1,%2;":"=l"(d):"l"(a),"l"(b)); return d; }

// ---------------- scratch ----------------
__device__ float g_q[Tc*Dc];
__device__ float g_k[Tc*Dc];
__device__ float g_v[Tc*Dc];
__device__ float g_gate[Tc*Dc];
__device__ float g_beta[Tc*Hc];
__device__ float g_egamma[Tc*Hc];
__device__ float g_w[Tc*Ec];
__device__ float g_o[(size_t)Ec*Tc*Hc*64];
__device__ float g_core[Tc*Dc];
__device__ int   g_list[Ec*Bc*Lc];
__device__ int   g_cnt[Ec*Bc];

// ---------------- multi-B GEMM: C[z] = act(A @ B[z]) ----------------
// BM=64, BN=64, BK=16, 128 threads. act: 0 none, 1 silu, 2 silu+l2norm(per 64-col head)
struct GemmBatch {
    const float* B[4];
    float*       C[4];
    int          act[4];
};

__global__ void __launch_bounds__(128) gemm_kernel(
        const float* __restrict__ A, GemmBatch gb, int K, int N) {
    __shared__ float As[16][68];
    __shared__ float Bs[16][64];
    int z = blockIdx.z;
    const float* __restrict__ B = gb.B[z];
    float* __restrict__ C = gb.C[z];
    int act = gb.act[z];

    int tid = threadIdx.x;
    int tx = tid & 15;
    int ty = tid >> 4;
    int m0 = blockIdx.y * 64;
    int n0 = blockIdx.x * 64;

    u64 acc2[4][4];
    #pragma unroll
    for (int i = 0; i < 4; i++)
        #pragma unroll
        for (int j = 0; j < 4; j++) acc2[i][j] = 0ull;

    for (int kt = 0; kt < K; kt += 16) {
        #pragma unroll
        for (int p = 0; p < 2; p++) {
            int idx = tid + p*128;
            int m  = idx >> 2;
            int k4 = (idx & 3) * 4;
            float4 v = *(const float4*)&A[(size_t)(m0 + m)*K + kt + k4];
            As[k4+0][m] = v.x; As[k4+1][m] = v.y;
            As[k4+2][m] = v.z; As[k4+3][m] = v.w;
        }
        #pragma unroll
        for (int p = 0; p < 2; p++) {
            int idx = tid + p*128;
            int k  = idx >> 4;
            int n4 = (idx & 15) * 4;
            *(float4*)&Bs[k][n4] = *(const float4*)&B[(size_t)(kt + k)*N + n0 + n4];
        }
        __syncthreads();
        #pragma unroll
        for (int kk = 0; kk < 16; kk++) {
            u64 av[4];
            #pragma unroll
            for (int ri = 0; ri < 4; ri++)
                av[ri] = *(const u64*)&As[kk][ty*8 + 2*ri];
            float4 bv = *(const float4*)&Bs[kk][tx*4];
            u64 bb[4] = { pk2(bv.x,bv.x), pk2(bv.y,bv.y), pk2(bv.z,bv.z), pk2(bv.w,bv.w) };
            #pragma unroll
            for (int ri = 0; ri < 4; ri++)
                #pragma unroll
                for (int j = 0; j < 4; j++)
                    acc2[ri][j] = fma2v(av[ri], bb[j], acc2[ri][j]);
        }
        __syncthreads();
    }

    #pragma unroll
    for (int ri = 0; ri < 4; ri++) {
        float r0[4], r1[4];
        #pragma unroll
        for (int j = 0; j < 4; j++) {
            float2 c = up2(acc2[ri][j]);
            r0[j] = c.x; r1[j] = c.y;
        }
        if (act >= 1) {
            #pragma unroll
            for (int j = 0; j < 4; j++) {
                r0[j] = r0[j] / (1.f + expf(-r0[j]));
                r1[j] = r1[j] / (1.f + expf(-r1[j]));
            }
        }
        if (act == 2) {
            // l2norm over 64 cols of this row: reduce across the 16-lane tx group
            float s0 = r0[0]*r0[0] + r0[1]*r0[1] + r0[2]*r0[2] + r0[3]*r0[3];
            float s1 = r1[0]*r1[0] + r1[1]*r1[1] + r1[2]*r1[2] + r1[3]*r1[3];
            #pragma unroll
            for (int off = 1; off < 16; off <<= 1) {
                s0 += __shfl_xor_sync(~0u, s0, off);
                s1 += __shfl_xor_sync(~0u, s1, off);
            }
            float n0f = rsqrtf(s0 + 1e-6f);
            float n1f = rsqrtf(s1 + 1e-6f);
            #pragma unroll
            for (int j = 0; j < 4; j++) { r0[j] *= n0f; r1[j] *= n1f; }
        }
        int m = m0 + ty*8 + 2*ri;
        *(float4*)&C[(size_t)m*N + n0 + tx*4]     = make_float4(r0[0],r0[1],r0[2],r0[3]);
        *(float4*)&C[(size_t)(m+1)*N + n0 + tx*4] = make_float4(r1[0],r1[1],r1[2],r1[3]);
    }
}

// ---------------- small projections: beta, exp(gamma), router top-2 ----------------
__global__ void smallproj_kernel(const float* __restrict__ h,
                                 const float* __restrict__ Wb,
                                 const float* __restrict__ Wa,
                                 const float* __restrict__ Wgate,
                                 const float* __restrict__ A_log,
                                 const float* __restrict__ dt_bias) {
    int warp = (blockIdx.x * blockDim.x + threadIdx.x) >> 5;
    int lane = threadIdx.x & 31;
    if (warp >= Tc) return;
    const float* hrow = h + (size_t)warp * Dc;

    float accB[Hc] = {}, accA[Hc] = {}, accG[Ec] = {};
    for (int i = 0; i < Dc/32; i++) {
        int r = i*32 + lane;
        float hv = hrow[r];
        #pragma unroll
        for (int c = 0; c < Hc; c++) {
            accB[c] = fmaf(hv, Wb[r*Hc + c], accB[c]);
            accA[c] = fmaf(hv, Wa[r*Hc + c], accA[c]);
        }
        #pragma unroll
        for (int c = 0; c < Ec; c++)
            accG[c] = fmaf(hv, Wgate[r*Ec + c], accG[c]);
    }
    #pragma unroll
    for (int c = 0; c < Hc; c++) {
        #pragma unroll
        for (int off = 16; off; off >>= 1) {
            accB[c] += __shfl_xor_sync(~0u, accB[c], off);
            accA[c] += __shfl_xor_sync(~0u, accA[c], off);
        }
    }
    #pragma unroll
    for (int c = 0; c < Ec; c++)
        #pragma unroll
        for (int off = 16; off; off >>= 1)
            accG[c] += __shfl_xor_sync(~0u, accG[c], off);

    if (lane < Hc) {
        int c = lane;
        g_beta[warp*Hc + c] = 1.f / (1.f + expf(-accB[c]));
        float x = accA[c] + dt_bias[c];
        float sp = (x > 20.f) ? x : log1pf(expf(x));
        g_egamma[warp*Hc + c] = expf(-expf(A_log[c]) * sp);
    }
    if (lane == 0) {
        float m = fmaxf(fmaxf(accG[0], accG[1]), fmaxf(accG[2], accG[3]));
        float p[4]; float s = 0.f;
        #pragma unroll
        for (int e = 0; e < 4; e++) { p[e] = expf(accG[e] - m); s += p[e]; }
        #pragma unroll
        for (int e = 0; e < 4; e++) p[e] /= s;
        int i1 = 0;
        for (int e = 1; e < 4; e++) if (p[e] > p[i1]) i1 = e;
        int i2 = -1;
        for (int e = 0; e < 4; e++) { if (e == i1) continue; if (i2 < 0 || p[e] > p[i2]) i2 = e; }
        float den = p[i1] + p[i2];
        float w[4] = {0.f, 0.f, 0.f, 0.f};
        w[i1] = p[i1] / den;
        w[i2] = p[i2] / den;
        #pragma unroll
        for (int e = 0; e < 4; e++) g_w[warp*Ec + e] = w[e];
    }
}

// ---------------- compact routed-token lists: one block per (e,b) ----------------
__global__ void __launch_bounds__(1024) compact_kernel() {
    int eb = blockIdx.x;
    int e = eb >> 2, b = eb & 3;
    int l = threadIdx.x;
    int warp = l >> 5, lane = l & 31;
    int t = b*Lc + l;
    bool on = g_w[t*Ec + e] > 0.f;
    unsigned mask = __ballot_sync(~0u, on);
    int pre = __popc(mask & ((1u << lane) - 1));
    __shared__ int wtot[32];
    if (lane == 31) wtot[warp] = pre + (on ? 1 : 0);
    __syncthreads();
    if (warp == 0) {
        int v = wtot[lane];
        #pragma unroll
        for (int off = 1; off < 32; off <<= 1) {
            int u = __shfl_up_sync(~0u, v, off);
            if (lane >= off) v += u;
        }
        wtot[lane] = v;
    }
    __syncthreads();
    int base = warp ? wtot[warp-1] : 0;
    if (on) g_list[eb*Lc + base + pre] = l;
    if (l == 1023) g_cnt[eb] = wtot[31];
}

// ---------------- scan: one block per (e,b,h), 256 thr, tid = j*4 + r ----------------
// thread handles rows [16r,16r+16) of column j; shfl reductions; pipelined loads.
__global__ void __launch_bounds__(256) scan_kernel() {
    int idx = blockIdx.x;            // e*32 + b*8 + h
    int e = idx >> 5;
    int b = (idx >> 3) & 3;
    int h = idx & 7;
    int tid = threadIdx.x;
    int j = tid >> 2;
    int r = tid & 3;
    int i0 = r << 4;

    __shared__ float kbuf[2][64], qbuf[2][64], vbuf[2][64];
    __shared__ float sc[2][2];       // eg, beta
    __shared__ int   stok[2];

    u64 S2[8];
    #pragma unroll
    for (int p = 0; p < 8; p++) S2[p] = 0ull;

    int eb = e*Bc + b;
    int cnt = g_cnt[eb];
    if (cnt == 0) return;
    const int* lst = &g_list[eb*Lc];

    int prole = tid >> 6;            // 0=k,1=q,2=v
    int pjj   = tid & 63;

    // preload token 0
    {
        int t = b*Lc + lst[0];
        size_t base = ((size_t)t*Hc + h) * 64;
        if (tid < 192) {
            float x = (prole==0) ? g_k[base+pjj] : (prole==1) ? g_q[base+pjj] : g_v[base+pjj];
            float* dst = (prole==0) ? kbuf[0] : (prole==1) ? qbuf[0] : vbuf[0];
            dst[pjj] = x;
        }
        if (tid == 192) sc[0][0] = g_egamma[t*Hc + h];
        if (tid == 193) sc[0][1] = g_beta[t*Hc + h];
        if (tid == 194) stok[0] = t;
    }
    __syncthreads();

    for (int n = 0; n < cnt; n++) {
        int cur = n & 1, nxt = cur ^ 1;

        // ---- prefetch LDGs for token n+1 (issued before compute) ----
        bool do_pf = (n + 1 < cnt);
        float pf = 0.f, peg = 0.f, pbt = 0.f;
        int t2 = 0;
        if (do_pf) {
            t2 = b*Lc + lst[n+1];
            if (tid < 192) {
                size_t base2 = ((size_t)t2*Hc + h) * 64;
                pf = (prole==0) ? g_k[base2+pjj] : (prole==1) ? g_q[base2+pjj] : g_v[base2+pjj];
            } else if (tid == 192) peg = g_egamma[t2*Hc + h];
            else if (tid == 193) pbt = g_beta[t2*Hc + h];
        }

        // ---- compute token n ----
        float eg  = sc[cur][0];
        float bet = sc[cur][1];
        int   t   = stok[cur];
        u64 eg2 = pk2(eg, eg);

        u64 k2[8];
        u64 kv2 = 0ull;
        #pragma unroll
        for (int p = 0; p < 8; p++) {
            k2[p] = *(const u64*)&kbuf[cur][i0 + 2*p];
            S2[p] = mul2v(S2[p], eg2);
            kv2 = fma2v(k2[p], S2[p], kv2);
        }
        float2 kvf = up2(kv2);
        float kv = kvf.x + kvf.y;
        kv += __shfl_xor_sync(~0u, kv, 1);
        kv += __shfl_xor_sync(~0u, kv, 2);
        float delta = (vbuf[cur][j] - kv) * bet;
        u64 d2 = pk2(delta, delta);

        u64 o2 = 0ull;
        #pragma unroll
        for (int p = 0; p < 8; p++) {
            u64 q2 = *(const u64*)&qbuf[cur][i0 + 2*p];
            S2[p] = fma2v(k2[p], d2, S2[p]);
            o2 = fma2v(q2, S2[p], o2);
        }
        float2 of = up2(o2);
        float o = of.x + of.y;
        o += __shfl_xor_sync(~0u, o, 1);
        o += __shfl_xor_sync(~0u, o, 2);
        if (r == 0)
            g_o[(((size_t)e*Tc + t)*Hc + h)*64 + j] = o * 0.125f;

        // ---- commit prefetched data to smem ----
        if (do_pf) {
            if (tid < 192) {
                float* dst = (prole==0) ? kbuf[nxt] : (prole==1) ? qbuf[nxt] : vbuf[nxt];
                dst[pjj] = pf;
            } else if (tid == 192) sc[nxt][0] = peg;
            else if (tid == 193) sc[nxt][1] = pbt;
            else if (tid == 194) stok[nxt] = t2;
        }
        __syncthreads();
    }
}

// ---------------- combine experts + gated RMSNorm ----------------
__global__ void combine_kernel(const float* __restrict__ onw) {
    int t    = blockIdx.x;
    int h    = threadIdx.x >> 5;
    int lane = threadIdx.x & 31;

    float w[4];
    #pragma unroll
    for (int e = 0; e < 4; e++) w[e] = g_w[t*Ec + e];

    float c0 = 0.f, c1 = 0.f;
    #pragma unroll
    for (int e = 0; e < 4; e++) {
        if (w[e] > 0.f) {
            size_t base = (((size_t)e*Tc + t)*Hc + h) * 64;
            c0 = fmaf(w[e], g_o[base + lane],      c0);
            c1 = fmaf(w[e], g_o[base + lane + 32], c1);
        }
    }
    float ss = c0*c0 + c1*c1;
    #pragma unroll
    for (int off = 16; off; off >>= 1) ss += __shfl_xor_sync(~0u, ss, off);
    float r = rsqrtf(ss * (1.f/64.f) + 1e-5f);

    size_t gb = (size_t)t*Dc + h*64;
    float gt0 = g_gate[gb + lane];
    float gt1 = g_gate[gb + lane + 32];
    g_core[gb + lane]      = c0 * r * onw[lane]      * gt0;
    g_core[gb + lane + 32] = c1 * r * onw[lane + 32] * gt1;
}

// ---------------- launcher ----------------
extern "C" void kernel_launch(void* const* d_in, const int* in_sizes, int n_in,
                              void* d_out, int out_size) {
    const float* h     = (const float*)d_in[0];
    const float* Wq    = (const float*)d_in[1];
    const float* Wgate = (const float*)d_in[2];
    const float* Wk    = (const float*)d_in[3];
    const float* Wv    = (const float*)d_in[4];
    const float* Wb    = (const float*)d_in[5];
    const float* Wa    = (const float*)d_in[6];
    const float* A_log = (const float*)d_in[7];
    const float* dtb   = (const float*)d_in[8];
    const float* Wg    = (const float*)d_in[9];
    const float* onw   = (const float*)d_in[10];
    const float* Wo    = (const float*)d_in[11];
    float* out = (float*)d_out;

    float *pq, *pk, *pv, *pg, *pcore;
    cudaGetSymbolAddress((void**)&pq, g_q);
    cudaGetSymbolAddress((void**)&pk, g_k);
    cudaGetSymbolAddress((void**)&pv, g_v);
    cudaGetSymbolAddress((void**)&pg, g_gate);
    cudaGetSymbolAddress((void**)&pcore, g_core);

    // fused 4-way projection GEMM (q,k: silu+l2norm; v,g: silu)
    GemmBatch gb4;
    gb4.B[0] = Wq; gb4.C[0] = pq; gb4.act[0] = 2;
    gb4.B[1] = Wk; gb4.C[1] = pk; gb4.act[1] = 2;
    gb4.B[2] = Wv; gb4.C[2] = pv; gb4.act[2] = 1;
    gb4.B[3] = Wg; gb4.C[3] = pg; gb4.act[3] = 1;
    dim3 g4(Dc/64, Tc/64, 4);
    gemm_kernel<<<g4, 128>>>(h, gb4, Dc, Dc);

    smallproj_kernel<<<Tc/8, 256>>>(h, Wb, Wa, Wgate, A_log, dtb);
    compact_kernel<<<Ec*Bc, 1024>>>();
    scan_kernel<<<128, 256>>>();
    combine_kernel<<<Tc, 256>>>(onw);

    GemmBatch gbo;
    gbo.B[0] = Wo; gbo.C[0] = out; gbo.act[0] = 0;
    gbo.B[1] = Wo; gbo.C[1] = out; gbo.act[1] = 0;
    gbo.B[2] = Wo; gbo.C[2] = out; gbo.act[2] = 0;
    gbo.B[3] = Wo; gbo.C[3] = out; gbo.act[3] = 0;
    dim3 g1(Dc/64, Tc/64, 1);
    gemm_kernel<<<g1, 128>>>(pcore, gbo, Dc, Dc);
}

// round 4
// speedup vs baseline: 1.5790x; 1.2251x over previous
#include <cuda_runtime.h>
#include <math.h>

#define Bc  4
#define Lc  1024
#define Dc  512
#define Hc  8
#define Ec  4
#define Tc  (Bc*Lc)       // 4096 tokens

typedef unsigned long long u64;

__device__ __forceinline__ u64 pk2(float x, float y){ u64 r; asm("mov.b64 %0,{%1,%2};":"=l"(r):"f"(x),"f"(y)); return r; }
__device__ __forceinline__ float2 up2(u64 v){ float2 r; asm("mov.b64 {%0,%1},%2;":"=f"(r.x),"=f"(r.y):"l"(v)); return r; }
__device__ __forceinline__ u64 fma2v(u64 a,u64 b,u64 c){ u64 d; asm("fma.rn.f32x2 %0,%1,%2,%3;":"=l"(d):"l"(a),"l"(b),"l"(c)); return d; }
__device__ __forceinline__ u64 mul2v(u64 a,u64 b){ u64 d; asm("mul.rn.f32x2 %0,%1,%2;":"=l"(d):"l"(a),"l"(b)); return d; }

// ---------------- scratch ----------------
__device__ float g_q[Tc*Dc];
__device__ float g_k[Tc*Dc];
__device__ float g_v[Tc*Dc];
__device__ float g_gate[Tc*Dc];
__device__ float2 g_eb[Tc*Hc];     // (exp(gamma), beta) packed
__device__ float g_w[Tc*Ec];
__device__ float g_o[(size_t)Ec*Tc*Hc*64];
__device__ float g_core[Tc*Dc];
__device__ int   g_list[Ec*Bc*Lc];
__device__ int   g_cnt[Ec*Bc];

// ---------------- multi-B GEMM: C[z] = act(A @ B[z]) ----------------
struct GemmBatch {
    const float* B[4];
    float*       C[4];
    int          act[4];
};

__global__ void __launch_bounds__(128) gemm_kernel(
        const float* __restrict__ A, GemmBatch gb, int K, int N) {
    __shared__ float As[16][68];
    __shared__ float Bs[16][64];
    int z = blockIdx.z;
    const float* __restrict__ B = gb.B[z];
    float* __restrict__ C = gb.C[z];
    int act = gb.act[z];

    int tid = threadIdx.x;
    int tx = tid & 15;
    int ty = tid >> 4;
    int m0 = blockIdx.y * 64;
    int n0 = blockIdx.x * 64;

    u64 acc2[4][4];
    #pragma unroll
    for (int i = 0; i < 4; i++)
        #pragma unroll
        for (int j = 0; j < 4; j++) acc2[i][j] = 0ull;

    for (int kt = 0; kt < K; kt += 16) {
        #pragma unroll
        for (int p = 0; p < 2; p++) {
            int idx = tid + p*128;
            int m  = idx >> 2;
            int k4 = (idx & 3) * 4;
            float4 v = *(const float4*)&A[(size_t)(m0 + m)*K + kt + k4];
            As[k4+0][m] = v.x; As[k4+1][m] = v.y;
            As[k4+2][m] = v.z; As[k4+3][m] = v.w;
        }
        #pragma unroll
        for (int p = 0; p < 2; p++) {
            int idx = tid + p*128;
            int k  = idx >> 4;
            int n4 = (idx & 15) * 4;
            *(float4*)&Bs[k][n4] = *(const float4*)&B[(size_t)(kt + k)*N + n0 + n4];
        }
        __syncthreads();
        #pragma unroll
        for (int kk = 0; kk < 16; kk++) {
            u64 av[4];
            #pragma unroll
            for (int ri = 0; ri < 4; ri++)
                av[ri] = *(const u64*)&As[kk][ty*8 + 2*ri];
            float4 bv = *(const float4*)&Bs[kk][tx*4];
            u64 bb[4] = { pk2(bv.x,bv.x), pk2(bv.y,bv.y), pk2(bv.z,bv.z), pk2(bv.w,bv.w) };
            #pragma unroll
            for (int ri = 0; ri < 4; ri++)
                #pragma unroll
                for (int j = 0; j < 4; j++)
                    acc2[ri][j] = fma2v(av[ri], bb[j], acc2[ri][j]);
        }
        __syncthreads();
    }

    #pragma unroll
    for (int ri = 0; ri < 4; ri++) {
        float r0[4], r1[4];
        #pragma unroll
        for (int j = 0; j < 4; j++) {
            float2 c = up2(acc2[ri][j]);
            r0[j] = c.x; r1[j] = c.y;
        }
        if (act >= 1) {
            #pragma unroll
            for (int j = 0; j < 4; j++) {
                r0[j] = r0[j] / (1.f + expf(-r0[j]));
                r1[j] = r1[j] / (1.f + expf(-r1[j]));
            }
        }
        if (act == 2) {
            float s0 = r0[0]*r0[0] + r0[1]*r0[1] + r0[2]*r0[2] + r0[3]*r0[3];
            float s1 = r1[0]*r1[0] + r1[1]*r1[1] + r1[2]*r1[2] + r1[3]*r1[3];
            #pragma unroll
            for (int off = 1; off < 16; off <<= 1) {
                s0 += __shfl_xor_sync(~0u, s0, off);
                s1 += __shfl_xor_sync(~0u, s1, off);
            }
            float n0f = rsqrtf(s0 + 1e-6f);
            float n1f = rsqrtf(s1 + 1e-6f);
            #pragma unroll
            for (int j = 0; j < 4; j++) { r0[j] *= n0f; r1[j] *= n1f; }
        }
        int m = m0 + ty*8 + 2*ri;
        *(float4*)&C[(size_t)m*N + n0 + tx*4]     = make_float4(r0[0],r0[1],r0[2],r0[3]);
        *(float4*)&C[(size_t)(m+1)*N + n0 + tx*4] = make_float4(r1[0],r1[1],r1[2],r1[3]);
    }
}

// ---------------- small projections: (exp(gamma),beta), router top-2 ----------------
__global__ void smallproj_kernel(const float* __restrict__ h,
                                 const float* __restrict__ Wb,
                                 const float* __restrict__ Wa,
                                 const float* __restrict__ Wgate,
                                 const float* __restrict__ A_log,
                                 const float* __restrict__ dt_bias) {
    int warp = (blockIdx.x * blockDim.x + threadIdx.x) >> 5;
    int lane = threadIdx.x & 31;
    if (warp >= Tc) return;
    const float* hrow = h + (size_t)warp * Dc;

    float accB[Hc] = {}, accA[Hc] = {}, accG[Ec] = {};
    for (int i = 0; i < Dc/32; i++) {
        int r = i*32 + lane;
        float hv = hrow[r];
        #pragma unroll
        for (int c = 0; c < Hc; c++) {
            accB[c] = fmaf(hv, Wb[r*Hc + c], accB[c]);
            accA[c] = fmaf(hv, Wa[r*Hc + c], accA[c]);
        }
        #pragma unroll
        for (int c = 0; c < Ec; c++)
            accG[c] = fmaf(hv, Wgate[r*Ec + c], accG[c]);
    }
    #pragma unroll
    for (int c = 0; c < Hc; c++) {
        #pragma unroll
        for (int off = 16; off; off >>= 1) {
            accB[c] += __shfl_xor_sync(~0u, accB[c], off);
            accA[c] += __shfl_xor_sync(~0u, accA[c], off);
        }
    }
    #pragma unroll
    for (int c = 0; c < Ec; c++)
        #pragma unroll
        for (int off = 16; off; off >>= 1)
            accG[c] += __shfl_xor_sync(~0u, accG[c], off);

    if (lane < Hc) {
        int c = lane;
        float bet = 1.f / (1.f + expf(-accB[c]));
        float x = accA[c] + dt_bias[c];
        float sp = (x > 20.f) ? x : log1pf(expf(x));
        float eg = expf(-expf(A_log[c]) * sp);
        g_eb[warp*Hc + c] = make_float2(eg, bet);
    }
    if (lane == 0) {
        float m = fmaxf(fmaxf(accG[0], accG[1]), fmaxf(accG[2], accG[3]));
        float p[4]; float s = 0.f;
        #pragma unroll
        for (int e = 0; e < 4; e++) { p[e] = expf(accG[e] - m); s += p[e]; }
        #pragma unroll
        for (int e = 0; e < 4; e++) p[e] /= s;
        int i1 = 0;
        for (int e = 1; e < 4; e++) if (p[e] > p[i1]) i1 = e;
        int i2 = -1;
        for (int e = 0; e < 4; e++) { if (e == i1) continue; if (i2 < 0 || p[e] > p[i2]) i2 = e; }
        float den = p[i1] + p[i2];
        float w[4] = {0.f, 0.f, 0.f, 0.f};
        w[i1] = p[i1] / den;
        w[i2] = p[i2] / den;
        #pragma unroll
        for (int e = 0; e < 4; e++) g_w[warp*Ec + e] = w[e];
    }
}

// ---------------- compact routed-token lists ----------------
__global__ void __launch_bounds__(1024) compact_kernel() {
    int eb = blockIdx.x;
    int e = eb >> 2, b = eb & 3;
    int l = threadIdx.x;
    int warp = l >> 5, lane = l & 31;
    int t = b*Lc + l;
    bool on = g_w[t*Ec + e] > 0.f;
    unsigned mask = __ballot_sync(~0u, on);
    int pre = __popc(mask & ((1u << lane) - 1));
    __shared__ int wtot[32];
    if (lane == 31) wtot[warp] = pre + (on ? 1 : 0);
    __syncthreads();
    if (warp == 0) {
        int v = wtot[lane];
        #pragma unroll
        for (int off = 1; off < 32; off <<= 1) {
            int u = __shfl_up_sync(~0u, v, off);
            if (lane >= off) v += u;
        }
        wtot[lane] = v;
    }
    __syncthreads();
    int base = warp ? wtot[warp-1] : 0;
    if (on) g_list[eb*Lc + base + pre] = l;
    if (l == 1023) g_cnt[eb] = wtot[31];
}

// ---------------- barrier-free scan ----------------
// block = (e,b,h), 256 threads. lane = j_local*4 + r; warp handles 8 columns.
// thread owns rows [16r,16r+16) of column j. Reductions: shfl.xor 1,2 only.
struct Tok {
    float4 k[4], q[4];
    float  v;
    float2 eb;
    int    t;
};

__device__ __forceinline__ void tok_load(Tok& T, int t, int h, int i0, int j) {
    size_t kb = ((size_t)t*Hc + h) * 64 + i0;
    T.k[0] = *(const float4*)&g_k[kb];
    T.k[1] = *(const float4*)&g_k[kb + 4];
    T.k[2] = *(const float4*)&g_k[kb + 8];
    T.k[3] = *(const float4*)&g_k[kb + 12];
    T.q[0] = *(const float4*)&g_q[kb];
    T.q[1] = *(const float4*)&g_q[kb + 4];
    T.q[2] = *(const float4*)&g_q[kb + 8];
    T.q[3] = *(const float4*)&g_q[kb + 12];
    T.v    = g_v[((size_t)t*Hc + h) * 64 + j];
    T.eb   = g_eb[t*Hc + h];
    T.t    = t;
}

__device__ __forceinline__ void tok_step(u64 S2[8], const Tok& T,
                                         int e, int h, int j, int r) {
    u64 eg2 = pk2(T.eb.x, T.eb.x);
    u64 k2[8];
    #pragma unroll
    for (int p = 0; p < 4; p++) {
        k2[2*p]   = pk2(T.k[p].x, T.k[p].y);
        k2[2*p+1] = pk2(T.k[p].z, T.k[p].w);
    }
    u64 kvA = 0ull, kvB = 0ull;
    #pragma unroll
    for (int p = 0; p < 4; p++) {
        S2[p]   = mul2v(S2[p],   eg2);
        S2[p+4] = mul2v(S2[p+4], eg2);
        kvA = fma2v(k2[p],   S2[p],   kvA);
        kvB = fma2v(k2[p+4], S2[p+4], kvB);
    }
    float2 ka = up2(kvA), kb = up2(kvB);
    float kv = (ka.x + ka.y) + (kb.x + kb.y);
    kv += __shfl_xor_sync(~0u, kv, 1);
    kv += __shfl_xor_sync(~0u, kv, 2);
    float delta = (T.v - kv) * T.eb.y;
    u64 d2 = pk2(delta, delta);

    u64 oA = 0ull, oB = 0ull;
    #pragma unroll
    for (int p = 0; p < 4; p++) {
        u64 qa = pk2(T.q[p].x, T.q[p].y);
        u64 qb = pk2(T.q[p].z, T.q[p].w);
        S2[2*p]   = fma2v(k2[2*p],   d2, S2[2*p]);
        S2[2*p+1] = fma2v(k2[2*p+1], d2, S2[2*p+1]);
        oA = fma2v(qa, S2[2*p],   oA);
        oB = fma2v(qb, S2[2*p+1], oB);
    }
    float2 oa = up2(oA), ob = up2(oB);
    float o = (oa.x + oa.y) + (ob.x + ob.y);
    o += __shfl_xor_sync(~0u, o, 1);
    o += __shfl_xor_sync(~0u, o, 2);
    if (r == 0)
        g_o[(((size_t)e*Tc + T.t)*Hc + h)*64 + j] = o * 0.125f;
}

__global__ void __launch_bounds__(256, 1) scan_kernel() {
    int idx = blockIdx.x;            // e*32 + b*8 + h
    int e = idx >> 5;
    int b = (idx >> 3) & 3;
    int h = idx & 7;
    int tid  = threadIdx.x;
    int lane = tid & 31;
    int warp = tid >> 5;
    int r  = lane & 3;
    int j  = warp * 8 + (lane >> 2);
    int i0 = r << 4;

    __shared__ int slist[Lc];

    int eb = e*Bc + b;
    int cnt = g_cnt[eb];
    if (cnt == 0) return;
    const int* lst = &g_list[eb*Lc];
    for (int i = tid; i < cnt; i += 256) slist[i] = b*Lc + lst[i];
    __syncthreads();

    u64 S2[8];
    #pragma unroll
    for (int p = 0; p < 8; p++) S2[p] = 0ull;

    Tok A, B;
    tok_load(A, slist[0], h, i0, j);
    if (cnt > 1) tok_load(B, slist[1], h, i0, j);

    for (int n = 0; n < cnt; n += 2) {
        tok_step(S2, A, e, h, j, r);
        if (n + 2 < cnt) tok_load(A, slist[n+2], h, i0, j);
        if (n + 1 < cnt) {
            tok_step(S2, B, e, h, j, r);
            if (n + 3 < cnt) tok_load(B, slist[n+3], h, i0, j);
        }
    }
}

// ---------------- combine experts + gated RMSNorm ----------------
__global__ void combine_kernel(const float* __restrict__ onw) {
    int t    = blockIdx.x;
    int h    = threadIdx.x >> 5;
    int lane = threadIdx.x & 31;

    float w[4];
    #pragma unroll
    for (int e = 0; e < 4; e++) w[e] = g_w[t*Ec + e];

    float c0 = 0.f, c1 = 0.f;
    #pragma unroll
    for (int e = 0; e < 4; e++) {
        if (w[e] > 0.f) {
            size_t base = (((size_t)e*Tc + t)*Hc + h) * 64;
            c0 = fmaf(w[e], g_o[base + lane],      c0);
            c1 = fmaf(w[e], g_o[base + lane + 32], c1);
        }
    }
    float ss = c0*c0 + c1*c1;
    #pragma unroll
    for (int off = 16; off; off >>= 1) ss += __shfl_xor_sync(~0u, ss, off);
    float r = rsqrtf(ss * (1.f/64.f) + 1e-5f);

    size_t gb = (size_t)t*Dc + h*64;
    float gt0 = g_gate[gb + lane];
    float gt1 = g_gate[gb + lane + 32];
    g_core[gb + lane]      = c0 * r * onw[lane]      * gt0;
    g_core[gb + lane + 32] = c1 * r * onw[lane + 32] * gt1;
}

// ---------------- launcher ----------------
extern "C" void kernel_launch(void* const* d_in, const int* in_sizes, int n_in,
                              void* d_out, int out_size) {
    const float* h     = (const float*)d_in[0];
    const float* Wq    = (const float*)d_in[1];
    const float* Wgate = (const float*)d_in[2];
    const float* Wk    = (const float*)d_in[3];
    const float* Wv    = (const float*)d_in[4];
    const float* Wb    = (const float*)d_in[5];
    const float* Wa    = (const float*)d_in[6];
    const float* A_log = (const float*)d_in[7];
    const float* dtb   = (const float*)d_in[8];
    const float* Wg    = (const float*)d_in[9];
    const float* onw   = (const float*)d_in[10];
    const float* Wo    = (const float*)d_in[11];
    float* out = (float*)d_out;

    float *pq, *pk, *pv, *pg, *pcore;
    cudaGetSymbolAddress((void**)&pq, g_q);
    cudaGetSymbolAddress((void**)&pk, g_k);
    cudaGetSymbolAddress((void**)&pv, g_v);
    cudaGetSymbolAddress((void**)&pg, g_gate);
    cudaGetSymbolAddress((void**)&pcore, g_core);

    GemmBatch gb4;
    gb4.B[0] = Wq; gb4.C[0] = pq; gb4.act[0] = 2;
    gb4.B[1] = Wk; gb4.C[1] = pk; gb4.act[1] = 2;
    gb4.B[2] = Wv; gb4.C[2] = pv; gb4.act[2] = 1;
    gb4.B[3] = Wg; gb4.C[3] = pg; gb4.act[3] = 1;
    dim3 g4(Dc/64, Tc/64, 4);
    gemm_kernel<<<g4, 128>>>(h, gb4, Dc, Dc);

    smallproj_kernel<<<Tc/8, 256>>>(h, Wb, Wa, Wgate, A_log, dtb);
    compact_kernel<<<Ec*Bc, 1024>>>();
    scan_kernel<<<128, 256>>>();
    combine_kernel<<<Tc, 256>>>(onw);

    GemmBatch gbo;
    gbo.B[0] = Wo; gbo.C[0] = out; gbo.act[0] = 0;
    gbo.B[1] = Wo; gbo.C[1] = out; gbo.act[1] = 0;
    gbo.B[2] = Wo; gbo.C[2] = out; gbo.act[2] = 0;
    gbo.B[3] = Wo; gbo.C[3] = out; gbo.act[3] = 0;
    dim3 g1(Dc/64, Tc/64, 1);
    gemm_kernel<<<g1, 128>>>(pcore, gbo, Dc, Dc);
}

// round 5
// speedup vs baseline: 1.7122x; 1.0844x over previous
#include <cuda_runtime.h>
#include <math.h>

#define Bc  4
#define Lc  1024
#define Dc  512
#define Hc  8
#define Ec  4
#define Tc  (Bc*Lc)       // 4096 tokens

typedef unsigned long long u64;

__device__ __forceinline__ u64 pk2(float x, float y){ u64 r; asm("mov.b64 %0,{%1,%2};":"=l"(r):"f"(x),"f"(y)); return r; }
__device__ __forceinline__ float2 up2(u64 v){ float2 r; asm("mov.b64 {%0,%1},%2;":"=f"(r.x),"=f"(r.y):"l"(v)); return r; }
__device__ __forceinline__ u64 fma2v(u64 a,u64 b,u64 c){ u64 d; asm("fma.rn.f32x2 %0,%1,%2,%3;":"=l"(d):"l"(a),"l"(b),"l"(c)); return d; }
__device__ __forceinline__ u64 mul2v(u64 a,u64 b){ u64 d; asm("mul.rn.f32x2 %0,%1,%2;":"=l"(d):"l"(a),"l"(b)); return d; }

// ---------------- scratch ----------------
__device__ float g_q[Tc*Dc];
__device__ float g_k[Tc*Dc];
__device__ float g_v[Tc*Dc];
__device__ float g_gate[Tc*Dc];
__device__ float2 g_eb[Tc*Hc];     // (exp(gamma), beta) packed
__device__ float g_w[Tc*Ec];
__device__ float g_o[(size_t)Ec*Tc*Hc*64];
__device__ float g_core[Tc*Dc];
__device__ int   g_list[Ec*Bc*Lc];
__device__ int   g_cnt[Ec*Bc];

// ---------------- multi-B GEMM: C[z] = act(A @ B[z]) ----------------
struct GemmBatch {
    const float* B[4];
    float*       C[4];
    int          act[4];
};

__global__ void __launch_bounds__(128) gemm_kernel(
        const float* __restrict__ A, GemmBatch gb, int K, int N) {
    __shared__ float As[16][68];
    __shared__ float Bs[16][64];
    int z = blockIdx.z;
    const float* __restrict__ B = gb.B[z];
    float* __restrict__ C = gb.C[z];
    int act = gb.act[z];

    int tid = threadIdx.x;
    int tx = tid & 15;
    int ty = tid >> 4;
    int m0 = blockIdx.y * 64;
    int n0 = blockIdx.x * 64;

    u64 acc2[4][4];
    #pragma unroll
    for (int i = 0; i < 4; i++)
        #pragma unroll
        for (int j = 0; j < 4; j++) acc2[i][j] = 0ull;

    for (int kt = 0; kt < K; kt += 16) {
        #pragma unroll
        for (int p = 0; p < 2; p++) {
            int idx = tid + p*128;
            int m  = idx >> 2;
            int k4 = (idx & 3) * 4;
            float4 v = *(const float4*)&A[(size_t)(m0 + m)*K + kt + k4];
            As[k4+0][m] = v.x; As[k4+1][m] = v.y;
            As[k4+2][m] = v.z; As[k4+3][m] = v.w;
        }
        #pragma unroll
        for (int p = 0; p < 2; p++) {
            int idx = tid + p*128;
            int k  = idx >> 4;
            int n4 = (idx & 15) * 4;
            *(float4*)&Bs[k][n4] = *(const float4*)&B[(size_t)(kt + k)*N + n0 + n4];
        }
        __syncthreads();
        #pragma unroll
        for (int kk = 0; kk < 16; kk++) {
            u64 av[4];
            #pragma unroll
            for (int ri = 0; ri < 4; ri++)
                av[ri] = *(const u64*)&As[kk][ty*8 + 2*ri];
            float4 bv = *(const float4*)&Bs[kk][tx*4];
            u64 bb[4] = { pk2(bv.x,bv.x), pk2(bv.y,bv.y), pk2(bv.z,bv.z), pk2(bv.w,bv.w) };
            #pragma unroll
            for (int ri = 0; ri < 4; ri++)
                #pragma unroll
                for (int j = 0; j < 4; j++)
                    acc2[ri][j] = fma2v(av[ri], bb[j], acc2[ri][j]);
        }
        __syncthreads();
    }

    #pragma unroll
    for (int ri = 0; ri < 4; ri++) {
        float r0[4], r1[4];
        #pragma unroll
        for (int j = 0; j < 4; j++) {
            float2 c = up2(acc2[ri][j]);
            r0[j] = c.x; r1[j] = c.y;
        }
        if (act >= 1) {
            #pragma unroll
            for (int j = 0; j < 4; j++) {
                r0[j] = r0[j] / (1.f + expf(-r0[j]));
                r1[j] = r1[j] / (1.f + expf(-r1[j]));
            }
        }
        if (act == 2) {
            float s0 = r0[0]*r0[0] + r0[1]*r0[1] + r0[2]*r0[2] + r0[3]*r0[3];
            float s1 = r1[0]*r1[0] + r1[1]*r1[1] + r1[2]*r1[2] + r1[3]*r1[3];
            #pragma unroll
            for (int off = 1; off < 16; off <<= 1) {
                s0 += __shfl_xor_sync(~0u, s0, off);
                s1 += __shfl_xor_sync(~0u, s1, off);
            }
            float n0f = rsqrtf(s0 + 1e-6f);
            float n1f = rsqrtf(s1 + 1e-6f);
            #pragma unroll
            for (int j = 0; j < 4; j++) { r0[j] *= n0f; r1[j] *= n1f; }
        }
        int m = m0 + ty*8 + 2*ri;
        *(float4*)&C[(size_t)m*N + n0 + tx*4]     = make_float4(r0[0],r0[1],r0[2],r0[3]);
        *(float4*)&C[(size_t)(m+1)*N + n0 + tx*4] = make_float4(r1[0],r1[1],r1[2],r1[3]);
    }
}

// ---------------- small projections ----------------
__global__ void smallproj_kernel(const float* __restrict__ h,
                                 const float* __restrict__ Wb,
                                 const float* __restrict__ Wa,
                                 const float* __restrict__ Wgate,
                                 const float* __restrict__ A_log,
                                 const float* __restrict__ dt_bias) {
    int warp = (blockIdx.x * blockDim.x + threadIdx.x) >> 5;
    int lane = threadIdx.x & 31;
    if (warp >= Tc) return;
    const float* hrow = h + (size_t)warp * Dc;

    float accB[Hc] = {}, accA[Hc] = {}, accG[Ec] = {};
    for (int i = 0; i < Dc/32; i++) {
        int r = i*32 + lane;
        float hv = hrow[r];
        #pragma unroll
        for (int c = 0; c < Hc; c++) {
            accB[c] = fmaf(hv, Wb[r*Hc + c], accB[c]);
            accA[c] = fmaf(hv, Wa[r*Hc + c], accA[c]);
        }
        #pragma unroll
        for (int c = 0; c < Ec; c++)
            accG[c] = fmaf(hv, Wgate[r*Ec + c], accG[c]);
    }
    #pragma unroll
    for (int c = 0; c < Hc; c++) {
        #pragma unroll
        for (int off = 16; off; off >>= 1) {
            accB[c] += __shfl_xor_sync(~0u, accB[c], off);
            accA[c] += __shfl_xor_sync(~0u, accA[c], off);
        }
    }
    #pragma unroll
    for (int c = 0; c < Ec; c++)
        #pragma unroll
        for (int off = 16; off; off >>= 1)
            accG[c] += __shfl_xor_sync(~0u, accG[c], off);

    if (lane < Hc) {
        int c = lane;
        float bet = 1.f / (1.f + expf(-accB[c]));
        float x = accA[c] + dt_bias[c];
        float sp = (x > 20.f) ? x : log1pf(expf(x));
        float eg = expf(-expf(A_log[c]) * sp);
        g_eb[warp*Hc + c] = make_float2(eg, bet);
    }
    if (lane == 0) {
        float m = fmaxf(fmaxf(accG[0], accG[1]), fmaxf(accG[2], accG[3]));
        float p[4]; float s = 0.f;
        #pragma unroll
        for (int e = 0; e < 4; e++) { p[e] = expf(accG[e] - m); s += p[e]; }
        #pragma unroll
        for (int e = 0; e < 4; e++) p[e] /= s;
        int i1 = 0;
        for (int e = 1; e < 4; e++) if (p[e] > p[i1]) i1 = e;
        int i2 = -1;
        for (int e = 0; e < 4; e++) { if (e == i1) continue; if (i2 < 0 || p[e] > p[i2]) i2 = e; }
        float den = p[i1] + p[i2];
        float w[4] = {0.f, 0.f, 0.f, 0.f};
        w[i1] = p[i1] / den;
        w[i2] = p[i2] / den;
        #pragma unroll
        for (int e = 0; e < 4; e++) g_w[warp*Ec + e] = w[e];
    }
}

// ---------------- compact routed-token lists ----------------
__global__ void __launch_bounds__(1024) compact_kernel() {
    int eb = blockIdx.x;
    int e = eb >> 2, b = eb & 3;
    int l = threadIdx.x;
    int warp = l >> 5, lane = l & 31;
    int t = b*Lc + l;
    bool on = g_w[t*Ec + e] > 0.f;
    unsigned mask = __ballot_sync(~0u, on);
    int pre = __popc(mask & ((1u << lane) - 1));
    __shared__ int wtot[32];
    if (lane == 31) wtot[warp] = pre + (on ? 1 : 0);
    __syncthreads();
    if (warp == 0) {
        int v = wtot[lane];
        #pragma unroll
        for (int off = 1; off < 32; off <<= 1) {
            int u = __shfl_up_sync(~0u, v, off);
            if (lane >= off) v += u;
        }
        wtot[lane] = v;
    }
    __syncthreads();
    int base = warp ? wtot[warp-1] : 0;
    if (on) g_list[eb*Lc + base + pre] = l;
    if (l == 1023) g_cnt[eb] = wtot[31];
}

// ---------------- barrier-free scan, 4-deep token pipeline ----------------
struct Tok {
    float4 k[4], q[4];
    float  v;
    float2 eb;
    int    t;
};

__device__ __forceinline__ void tok_load(Tok& T, int t, int h, int i0, int j) {
    size_t kb = ((size_t)t*Hc + h) * 64 + i0;
    T.k[0] = *(const float4*)&g_k[kb];
    T.k[1] = *(const float4*)&g_k[kb + 4];
    T.k[2] = *(const float4*)&g_k[kb + 8];
    T.k[3] = *(const float4*)&g_k[kb + 12];
    T.q[0] = *(const float4*)&g_q[kb];
    T.q[1] = *(const float4*)&g_q[kb + 4];
    T.q[2] = *(const float4*)&g_q[kb + 8];
    T.q[3] = *(const float4*)&g_q[kb + 12];
    T.v    = g_v[((size_t)t*Hc + h) * 64 + j];
    T.eb   = g_eb[t*Hc + h];
    T.t    = t;
}

__device__ __forceinline__ void tok_step(u64 S2[8], const Tok& T,
                                         int e, int h, int j, int r) {
    u64 eg2 = pk2(T.eb.x, T.eb.x);
    u64 k2[8];
    #pragma unroll
    for (int p = 0; p < 4; p++) {
        k2[2*p]   = pk2(T.k[p].x, T.k[p].y);
        k2[2*p+1] = pk2(T.k[p].z, T.k[p].w);
    }
    u64 kvA = 0ull, kvB = 0ull;
    #pragma unroll
    for (int p = 0; p < 4; p++) {
        S2[p]   = mul2v(S2[p],   eg2);
        S2[p+4] = mul2v(S2[p+4], eg2);
        kvA = fma2v(k2[p],   S2[p],   kvA);
        kvB = fma2v(k2[p+4], S2[p+4], kvB);
    }
    float2 ka = up2(kvA), kb = up2(kvB);
    float kv = (ka.x + ka.y) + (kb.x + kb.y);
    kv += __shfl_xor_sync(~0u, kv, 1);
    kv += __shfl_xor_sync(~0u, kv, 2);
    float delta = (T.v - kv) * T.eb.y;
    u64 d2 = pk2(delta, delta);

    u64 oA = 0ull, oB = 0ull;
    #pragma unroll
    for (int p = 0; p < 4; p++) {
        u64 qa = pk2(T.q[p].x, T.q[p].y);
        u64 qb = pk2(T.q[p].z, T.q[p].w);
        S2[2*p]   = fma2v(k2[2*p],   d2, S2[2*p]);
        S2[2*p+1] = fma2v(k2[2*p+1], d2, S2[2*p+1]);
        oA = fma2v(qa, S2[2*p],   oA);
        oB = fma2v(qb, S2[2*p+1], oB);
    }
    float2 oa = up2(oA), ob = up2(oB);
    float o = (oa.x + oa.y) + (ob.x + ob.y);
    o += __shfl_xor_sync(~0u, o, 1);
    o += __shfl_xor_sync(~0u, o, 2);
    if (r == 0)
        g_o[(((size_t)e*Tc + T.t)*Hc + h)*64 + j] = o * 0.125f;
}

__global__ void __launch_bounds__(256, 1) scan_kernel() {
    int idx = blockIdx.x;            // e*32 + b*8 + h
    int e = idx >> 5;
    int b = (idx >> 3) & 3;
    int h = idx & 7;
    int tid  = threadIdx.x;
    int lane = tid & 31;
    int warp = tid >> 5;
    int r  = lane & 3;
    int j  = warp * 8 + (lane >> 2);
    int i0 = r << 4;

    __shared__ int slist[Lc];

    int ebi = e*Bc + b;
    int cnt = g_cnt[ebi];
    if (cnt == 0) return;
    const int* lst = &g_list[ebi*Lc];
    for (int i = tid; i < cnt; i += 256) slist[i] = b*Lc + lst[i];
    __syncthreads();

    u64 S2[8];
    #pragma unroll
    for (int p = 0; p < 8; p++) S2[p] = 0ull;

    Tok T0, T1, T2, T3;
    tok_load(T0, slist[0], h, i0, j);
    if (cnt > 1) tok_load(T1, slist[1], h, i0, j);
    if (cnt > 2) tok_load(T2, slist[2], h, i0, j);
    if (cnt > 3) tok_load(T3, slist[3], h, i0, j);

    int n = 0;
    for (; n + 4 <= cnt; n += 4) {
        tok_step(S2, T0, e, h, j, r);
        if (n + 4 < cnt) tok_load(T0, slist[n+4], h, i0, j);
        tok_step(S2, T1, e, h, j, r);
        if (n + 5 < cnt) tok_load(T1, slist[n+5], h, i0, j);
        tok_step(S2, T2, e, h, j, r);
        if (n + 6 < cnt) tok_load(T2, slist[n+6], h, i0, j);
        tok_step(S2, T3, e, h, j, r);
        if (n + 7 < cnt) tok_load(T3, slist[n+7], h, i0, j);
    }
    if (n     < cnt) tok_step(S2, T0, e, h, j, r);
    if (n + 1 < cnt) tok_step(S2, T1, e, h, j, r);
    if (n + 2 < cnt) tok_step(S2, T2, e, h, j, r);
}

// ---------------- combine experts + gated RMSNorm ----------------
__global__ void combine_kernel(const float* __restrict__ onw) {
    int t    = blockIdx.x;
    int h    = threadIdx.x >> 5;
    int lane = threadIdx.x & 31;

    float w[4];
    #pragma unroll
    for (int e = 0; e < 4; e++) w[e] = g_w[t*Ec + e];

    float c0 = 0.f, c1 = 0.f;
    #pragma unroll
    for (int e = 0; e < 4; e++) {
        if (w[e] > 0.f) {
            size_t base = (((size_t)e*Tc + t)*Hc + h) * 64;
            c0 = fmaf(w[e], g_o[base + lane],      c0);
            c1 = fmaf(w[e], g_o[base + lane + 32], c1);
        }
    }
    float ss = c0*c0 + c1*c1;
    #pragma unroll
    for (int off = 16; off; off >>= 1) ss += __shfl_xor_sync(~0u, ss, off);
    float r = rsqrtf(ss * (1.f/64.f) + 1e-5f);

    size_t gb = (size_t)t*Dc + h*64;
    float gt0 = g_gate[gb + lane];
    float gt1 = g_gate[gb + lane + 32];
    g_core[gb + lane]      = c0 * r * onw[lane]      * gt0;
    g_core[gb + lane + 32] = c1 * r * onw[lane + 32] * gt1;
}

// ---------------- launcher ----------------
extern "C" void kernel_launch(void* const* d_in, const int* in_sizes, int n_in,
                              void* d_out, int out_size) {
    const float* h     = (const float*)d_in[0];
    const float* Wq    = (const float*)d_in[1];
    const float* Wgate = (const float*)d_in[2];
    const float* Wk    = (const float*)d_in[3];
    const float* Wv    = (const float*)d_in[4];
    const float* Wb    = (const float*)d_in[5];
    const float* Wa    = (const float*)d_in[6];
    const float* A_log = (const float*)d_in[7];
    const float* dtb   = (const float*)d_in[8];
    const float* Wg    = (const float*)d_in[9];
    const float* onw   = (const float*)d_in[10];
    const float* Wo    = (const float*)d_in[11];
    float* out = (float*)d_out;

    float *pq, *pk, *pv, *pg, *pcore;
    cudaGetSymbolAddress((void**)&pq, g_q);
    cudaGetSymbolAddress((void**)&pk, g_k);
    cudaGetSymbolAddress((void**)&pv, g_v);
    cudaGetSymbolAddress((void**)&pg, g_gate);
    cudaGetSymbolAddress((void**)&pcore, g_core);

    GemmBatch gb4;
    gb4.B[0] = Wq; gb4.C[0] = pq; gb4.act[0] = 2;
    gb4.B[1] = Wk; gb4.C[1] = pk; gb4.act[1] = 2;
    gb4.B[2] = Wv; gb4.C[2] = pv; gb4.act[2] = 1;
    gb4.B[3] = Wg; gb4.C[3] = pg; gb4.act[3] = 1;
    dim3 g4(Dc/64, Tc/64, 4);
    gemm_kernel<<<g4, 128>>>(h, gb4, Dc, Dc);

    smallproj_kernel<<<Tc/8, 256>>>(h, Wb, Wa, Wgate, A_log, dtb);
    compact_kernel<<<Ec*Bc, 1024>>>();
    scan_kernel<<<128, 256>>>();
    combine_kernel<<<Tc, 256>>>(onw);

    GemmBatch gbo;
    gbo.B[0] = Wo; gbo.C[0] = out; gbo.act[0] = 0;
    gbo.B[1] = Wo; gbo.C[1] = out; gbo.act[1] = 0;
    gbo.B[2] = Wo; gbo.C[2] = out; gbo.act[2] = 0;
    gbo.B[3] = Wo; gbo.C[3] = out; gbo.act[3] = 0;
    dim3 g1(Dc/64, Tc/64, 1);
    gemm_kernel<<<g1, 128>>>(pcore, gbo, Dc, Dc);
}